// round 2
// baseline (speedup 1.0000x reference)
#include <cuda_runtime.h>
#include <cstdint>

// Covariance pooling: y[b] = (1/M) X Xᵀ - μ μᵀ, X = x[b] as [C=128, M=4096].
// Path: tf32 mma.sync (HMMA fallback; tcgen05 unavailable on compute_103 PTX).
// Kernel 1: 128 CTAs = 64 batches x 2 K-halves, each CTA computes a 128x128
//           partial Gram (K=2048) + exact fp32 row sums, into device scratch.
// Kernel 2: 64 CTAs combine halves and apply mean subtraction.

#define DINLINE __device__ __forceinline__

static constexpr int Bn = 64;
static constexpr int Cn = 128;
static constexpr int Mn = 4096;
static constexpr int KSPLIT = 2;
static constexpr int KHALF = Mn / KSPLIT;    // 2048
static constexpr int KT = 32;                // k per tile
static constexpr int NKT = KHALF / KT;       // 64 tiles
static constexpr int PAD = 36;               // floats per SMEM row (pad for banks)

__device__ float g_part[KSPLIT * Bn][Cn * Cn];   // 8 MB scratch
__device__ float g_sums[KSPLIT * Bn][Cn];

DINLINE void mma_tf32(float d[4], const uint32_t a[4], const uint32_t b[2]) {
    asm volatile(
        "mma.sync.aligned.m16n8k8.row.col.f32.tf32.tf32.f32 "
        "{%0,%1,%2,%3}, {%4,%5,%6,%7}, {%8,%9}, {%0,%1,%2,%3};"
        : "+f"(d[0]), "+f"(d[1]), "+f"(d[2]), "+f"(d[3])
        : "r"(a[0]), "r"(a[1]), "r"(a[2]), "r"(a[3]), "r"(b[0]), "r"(b[1]));
}
DINLINE uint32_t to_tf32(float v) {
    uint32_t u;
    asm("cvt.rna.tf32.f32 %0, %1;" : "=r"(u) : "f"(v));
    return u;
}

__global__ __launch_bounds__(256, 1)
void covpool_partial(const float* __restrict__ x) {
    __shared__ uint32_t buf[2][Cn * PAD];
    const int t    = threadIdx.x;
    const int warp = t >> 5;
    const int lane = t & 31;
    const int cta  = blockIdx.x;           // 0..127
    const int s    = cta & 1;
    const int b    = cta >> 1;

    const int row  = t >> 1;               // 0..127, global-load row
    const int coff = (t & 1) * 16;         // 0 or 16 within k-tile
    const float* src = x + (size_t)b * Cn * Mn + (size_t)row * Mn
                         + (size_t)s * KHALF + coff;

    const int wm = (warp & 1) * 64;        // 64-row block
    const int wn = (warp >> 1) * 32;       // 32-col block
    const int g  = lane >> 2;
    const int tg = lane & 3;

    float acc[4][4][4];
#pragma unroll
    for (int im = 0; im < 4; im++)
#pragma unroll
        for (int in = 0; in < 4; in++)
#pragma unroll
            for (int j = 0; j < 4; j++) acc[im][in][j] = 0.0f;

    float rowsum = 0.0f;
    float4 st[4];

    // prologue: tile 0
#pragma unroll
    for (int i = 0; i < 4; i++)
        st[i] = __ldg((const float4*)(src + i * 4));
    {
        uint32_t* dst = &buf[0][row * PAD + coff];
#pragma unroll
        for (int i = 0; i < 4; i++) {
            rowsum += st[i].x + st[i].y + st[i].z + st[i].w;
            uint4 u = { to_tf32(st[i].x), to_tf32(st[i].y),
                        to_tf32(st[i].z), to_tf32(st[i].w) };
            *(uint4*)(dst + i * 4) = u;
        }
    }
    __syncthreads();

    for (int kt = 0; kt < NKT; kt++) {
        const bool more = (kt + 1 < NKT);
        if (more) {
            const float* nsrc = src + (kt + 1) * KT;
#pragma unroll
            for (int i = 0; i < 4; i++)
                st[i] = __ldg((const float4*)(nsrc + i * 4));
        }
        const uint32_t* S = buf[kt & 1];
#pragma unroll
        for (int ks = 0; ks < 4; ks++) {
            const int k0 = ks * 8;
            uint32_t afr[4][4];
#pragma unroll
            for (int im = 0; im < 4; im++) {
                const int r0 = wm + im * 16 + g;
                afr[im][0] = S[r0 * PAD + k0 + tg];
                afr[im][1] = S[(r0 + 8) * PAD + k0 + tg];
                afr[im][2] = S[r0 * PAD + k0 + tg + 4];
                afr[im][3] = S[(r0 + 8) * PAD + k0 + tg + 4];
            }
            uint32_t bfr[4][2];
#pragma unroll
            for (int in = 0; in < 4; in++) {
                const int rn = wn + in * 8 + g;
                bfr[in][0] = S[rn * PAD + k0 + tg];
                bfr[in][1] = S[rn * PAD + k0 + tg + 4];
            }
#pragma unroll
            for (int im = 0; im < 4; im++)
#pragma unroll
                for (int in = 0; in < 4; in++)
                    mma_tf32(acc[im][in], afr[im], bfr[in]);
        }
        if (more) {
            uint32_t* dst = &buf[(kt + 1) & 1][row * PAD + coff];
#pragma unroll
            for (int i = 0; i < 4; i++) {
                rowsum += st[i].x + st[i].y + st[i].z + st[i].w;
                uint4 u = { to_tf32(st[i].x), to_tf32(st[i].y),
                            to_tf32(st[i].z), to_tf32(st[i].w) };
                *(uint4*)(dst + i * 4) = u;
            }
        }
        __syncthreads();
    }

    // epilogue: partial Gram -> scratch
    float* gp = g_part[cta];
#pragma unroll
    for (int im = 0; im < 4; im++) {
        const int r0 = wm + im * 16 + g;
#pragma unroll
        for (int in = 0; in < 4; in++) {
            const int c0 = wn + in * 8 + 2 * tg;
            *(float2*)(gp + r0 * Cn + c0)       = make_float2(acc[im][in][0], acc[im][in][1]);
            *(float2*)(gp + (r0 + 8) * Cn + c0) = make_float2(acc[im][in][2], acc[im][in][3]);
        }
    }
    // row sums (pairs of threads share a row)
    rowsum += __shfl_xor_sync(0xffffffffu, rowsum, 1);
    if ((t & 1) == 0) g_sums[cta][row] = rowsum;
}

__global__ __launch_bounds__(256, 1)
void covpool_finish(float* __restrict__ y) {
    __shared__ float mu[Cn];
    const int t = threadIdx.x;
    const int b = blockIdx.x;
    if (t < Cn)
        mu[t] = (g_sums[2 * b][t] + g_sums[2 * b + 1][t]) * (1.0f / (float)Mn);
    __syncthreads();

    const float4* G0 = (const float4*)g_part[2 * b];
    const float4* G1 = (const float4*)g_part[2 * b + 1];
    float4* out = (float4*)(y + (size_t)b * Cn * Cn);
    const float4* mu4 = (const float4*)mu;
    const float invM = 1.0f / (float)Mn;
#pragma unroll
    for (int j = 0; j < 16; j++) {
        const int idx = t + j * 256;        // float4 index in [0,4096)
        const int r   = idx >> 5;
        const float mc = mu[r];
        const float4 m = mu4[idx & 31];
        const float4 a = G0[idx];
        const float4 c = G1[idx];
        float4 o;
        o.x = (a.x + c.x) * invM - mc * m.x;
        o.y = (a.y + c.y) * invM - mc * m.y;
        o.z = (a.z + c.z) * invM - mc * m.z;
        o.w = (a.w + c.w) * invM - mc * m.w;
        out[idx] = o;
    }
}

extern "C" void kernel_launch(void* const* d_in, const int* in_sizes, int n_in,
                              void* d_out, int out_size) {
    (void)in_sizes; (void)n_in; (void)out_size;
    const float* x = (const float*)d_in[0];
    float* y = (float*)d_out;
    covpool_partial<<<KSPLIT * Bn, 256>>>(x);
    covpool_finish<<<Bn, 256>>>(y);
}